// round 15
// baseline (speedup 1.0000x reference)
#include <cuda_runtime.h>
#include <cuda_fp16.h>

#define N_NODES 100000
#define N_EDGES 3200000
#define IN_DIM  128
#define HID     16
#define SB1     512
#define SCAN_BLOCKS ((N_NODES + SB1 - 1) / SB1)   // 196

// Scratch (device globals, ~17 MB). CRITICAL RULE (root cause of rounds 6-9
// failures): NEVER pass a __device__ symbol as a kernel argument from host
// code — the host-side shadow address gets passed, the kernel derefs a host
// VA, and HMM backs it with a 128 MiB device arena, tripping the harness
// mem-guard. All globals are referenced directly in device code.
__device__ __align__(16) __half g_buf[N_NODES * HID];  // hs1/hs2 fp16 (3.2 MB)
__device__ int g_srcs  [N_EDGES];                      // dst-sorted src ids (12.8 MB)
__device__ int g_cnt   [N_NODES];                      // in-degree
__device__ int g_cursor[N_NODES];                      // excl scan -> incl prefix
__device__ int g_bsum [SCAN_BLOCKS];
__device__ int g_bbase[256];
__device__ int g_is64;

// Fork-join stream/events, created at program load — BEFORE the harness's
// memory checkpoint and BEFORE graph capture starts. No device-memory APIs.
static cudaStream_t g_s2;
static cudaEvent_t  g_evFork, g_evJoin;
static struct _StreamInit {
    _StreamInit() {
        cudaStreamCreateWithFlags(&g_s2, cudaStreamNonBlocking);
        cudaEventCreateWithFlags(&g_evFork, cudaEventDisableTiming);
        cudaEventCreateWithFlags(&g_evJoin, cudaEventDisableTiming);
    }
} g_streamInit;

// ---------------------------------------------------------------------------
// K0: zero degree counts; thread 0 also detects edge_index dtype
// (int64 ids < 2^31 -> all odd 32-bit words zero).
__global__ void k_zero(const unsigned int* __restrict__ ei32) {
    int i = blockIdx.x * blockDim.x + threadIdx.x;
    if (i < N_NODES) g_cnt[i] = 0;
    if (i == 0) {
        int is64 = 1;
        #pragma unroll
        for (int k = 0; k < 64; k++)
            if (ei32[2 * k + 1] != 0u) { is64 = 0; break; }
        g_is64 = is64;
    }
}

// K1: in-degree histogram over dst (into g_cnt)
__global__ void k_hist(const void* __restrict__ ei) {
    int e = blockIdx.x * blockDim.x + threadIdx.x;
    if (e < N_EDGES) {
        int d;
        if (g_is64) d = (int)((const long long*)ei)[N_EDGES + e];
        else        d = ((const int*)ei)[N_EDGES + e];
        atomicAdd(&g_cnt[d], 1);
    }
}

// dinv = rsqrt(deg+1), straight from g_cnt (+1 = self loop)
__device__ __forceinline__ float dinv_of(int i) {
    return rsqrtf((float)g_cnt[i] + 1.0f);
}

// K2a: per-block exclusive scan: read g_cnt, write g_cursor; sums -> g_bsum
__global__ void k_scan1() {
    __shared__ int sh[SB1];
    const int t = threadIdx.x;
    const int i = blockIdx.x * SB1 + t;
    int v = (i < N_NODES) ? g_cnt[i] : 0;
    sh[t] = v;
    __syncthreads();
    #pragma unroll
    for (int o = 1; o < SB1; o <<= 1) {
        int a = (t >= o) ? sh[t - o] : 0;
        __syncthreads();
        sh[t] += a;
        __syncthreads();
    }
    if (i < N_NODES) g_cursor[i] = sh[t] - v;            // local exclusive
    if (t == SB1 - 1) g_bsum[blockIdx.x] = sh[SB1 - 1];  // block total
}

// K2b: scan the block sums (single block, 256 >= 196)
__global__ void k_scan2() {
    __shared__ int sh[256];
    const int t = threadIdx.x;
    int v = (t < SCAN_BLOCKS) ? g_bsum[t] : 0;
    sh[t] = v;
    __syncthreads();
    #pragma unroll
    for (int o = 1; o < 256; o <<= 1) {
        int a = (t >= o) ? sh[t - o] : 0;
        __syncthreads();
        sh[t] += a;
        __syncthreads();
    }
    g_bbase[t] = sh[t] - v;
}

// K2c: add block bases -> global exclusive prefix (= segment starts)
__global__ void k_scan3() {
    int i = blockIdx.x * blockDim.x + threadIdx.x;
    if (i < N_NODES) g_cursor[i] += g_bbase[i / SB1];
}

// K3: permute src ids into dst-sorted order. Cursors advance from exclusive
// prefix (start) to inclusive prefix (end); agg derives start = end - cnt.
__global__ void k_permute(const void* __restrict__ ei) {
    int e = blockIdx.x * blockDim.x + threadIdx.x;
    if (e >= N_EDGES) return;
    int s, d;
    if (g_is64) {
        const long long* p = (const long long*)ei;
        s = (int)p[e]; d = (int)p[N_EDGES + e];
    } else {
        const int* p = (const int*)ei;
        s = p[e]; d = p[N_EDGES + e];
    }
    int pos = atomicAdd(&g_cursor[d], 1);
    g_srcs[pos] = s;
}

// K4: hs1 = fp16( (x @ W1) * dinv[node] ) -> g_buf. 16 rows/block.
// Runs on the side stream, overlapped with scan+permute (needs only g_cnt).
__global__ void k_gemm1(const float* __restrict__ x, const float* __restrict__ W1) {
    __shared__ float xs[16][IN_DIM];
    __shared__ float ws[IN_DIM][HID];
    const int t = threadIdx.x;
    const int row0 = blockIdx.x * 16;

    #pragma unroll
    for (int i = t; i < IN_DIM * HID; i += 256)
        ws[i >> 4][i & 15] = W1[i];
    #pragma unroll
    for (int i = t; i < 16 * IN_DIM; i += 256)
        xs[i >> 7][i & 127] = x[row0 * IN_DIM + i];
    __syncthreads();

    const int r = t >> 4, c = t & 15;
    float s = 0.0f;
    #pragma unroll
    for (int k = 0; k < IN_DIM; k++)
        s = fmaf(xs[r][k], ws[k][c], s);

    const int node = row0 + r;
    g_buf[node * HID + c] = __float2half(s * dinv_of(node));
}

// ---------------------------------------------------------------------------
// fp16 gather core: 2 lanes per edge (p = lane&1 picks 16B half-row).
// Each lane accumulates 8 columns (p*8..p*8+7) in fp32. After xor-reduce over
// edge-slots, every lane with the same p holds the full sum for its 8 cols.
struct F8 { float4 a, b; };

__device__ __forceinline__ void fma8(F8& acc, uint4 v, float w) {
    float2 f0 = __half22float2(*reinterpret_cast<__half2*>(&v.x));
    float2 f1 = __half22float2(*reinterpret_cast<__half2*>(&v.y));
    float2 f2 = __half22float2(*reinterpret_cast<__half2*>(&v.z));
    float2 f3 = __half22float2(*reinterpret_cast<__half2*>(&v.w));
    acc.a.x = fmaf(f0.x, w, acc.a.x); acc.a.y = fmaf(f0.y, w, acc.a.y);
    acc.a.z = fmaf(f1.x, w, acc.a.z); acc.a.w = fmaf(f1.y, w, acc.a.w);
    acc.b.x = fmaf(f2.x, w, acc.b.x); acc.b.y = fmaf(f2.y, w, acc.b.y);
    acc.b.z = fmaf(f3.x, w, acc.b.z); acc.b.w = fmaf(f3.y, w, acc.b.w);
}

__device__ __forceinline__ F8 warp_gather16(int start, int cnt, int lane, int p) {
    const uint4* h4 = reinterpret_cast<const uint4*>(g_buf);
    F8 acc; acc.a = make_float4(0.f,0.f,0.f,0.f); acc.b = acc.a;
    for (int base = 0; base < cnt; base += 32) {
        const int m = cnt - base;
        int src_l = 0;
        float w_l = 0.0f;                     // 0 => inert
        if (lane < m) { src_l = g_srcs[start + base + lane]; w_l = 1.0f; }
        #pragma unroll
        for (int r = 0; r < 2; r++) {
            if (16 * r >= m) break;           // uniform per warp
            const int j = (lane >> 1) + 16 * r;
            const int   src = __shfl_sync(0xffffffffu, src_l, j);
            const float w   = __shfl_sync(0xffffffffu, w_l,   j);
            uint4 v = h4[src * 2 + p];
            fma8(acc, v, w);
        }
    }
    #pragma unroll
    for (int ofs = 2; ofs < 32; ofs <<= 1) {
        acc.a.x += __shfl_xor_sync(0xffffffffu, acc.a.x, ofs);
        acc.a.y += __shfl_xor_sync(0xffffffffu, acc.a.y, ofs);
        acc.a.z += __shfl_xor_sync(0xffffffffu, acc.a.z, ofs);
        acc.a.w += __shfl_xor_sync(0xffffffffu, acc.a.w, ofs);
        acc.b.x += __shfl_xor_sync(0xffffffffu, acc.b.x, ofs);
        acc.b.y += __shfl_xor_sync(0xffffffffu, acc.b.y, ofs);
        acc.b.z += __shfl_xor_sync(0xffffffffu, acc.b.z, ofs);
        acc.b.w += __shfl_xor_sync(0xffffffffu, acc.b.w, ofs);
    }
    return acc;
}

// K5: aggregation. dst[node] = (relu?)( bias + dinv*( hs[node] + sum hs[src] ) )
// dst is fp32 (d_out used as act scratch for layer 1, final out for layer 2).
__global__ void k_agg(const float* __restrict__ bias,
                      float* __restrict__ dst,
                      int relu) {
    const int warp = (blockIdx.x * blockDim.x + threadIdx.x) >> 5;
    if (warp >= N_NODES) return;
    const int lane = threadIdx.x & 31;
    const int node = warp;
    const int cnt   = g_cnt[node];
    const int start = g_cursor[node] - cnt;  // cursor is inclusive after permute
    const int p     = lane & 1;
    const float dnode = rsqrtf((float)cnt + 1.0f);

    F8 acc = warp_gather16(start, cnt, lane, p);

    if (lane < 2) {
        uint4 sv = reinterpret_cast<const uint4*>(g_buf)[node * 2 + p];
        F8 self; self.a = make_float4(0,0,0,0); self.b = self.a;
        fma8(self, sv, 1.0f);
        float4 bA = reinterpret_cast<const float4*>(bias)[p * 2];
        float4 bB = reinterpret_cast<const float4*>(bias)[p * 2 + 1];
        float4 oA, oB;
        oA.x = fmaf(acc.a.x + self.a.x, dnode, bA.x);
        oA.y = fmaf(acc.a.y + self.a.y, dnode, bA.y);
        oA.z = fmaf(acc.a.z + self.a.z, dnode, bA.z);
        oA.w = fmaf(acc.a.w + self.a.w, dnode, bA.w);
        oB.x = fmaf(acc.b.x + self.b.x, dnode, bB.x);
        oB.y = fmaf(acc.b.y + self.b.y, dnode, bB.y);
        oB.z = fmaf(acc.b.z + self.b.z, dnode, bB.z);
        oB.w = fmaf(acc.b.w + self.b.w, dnode, bB.w);
        if (relu) {
            oA.x = fmaxf(oA.x, 0.f); oA.y = fmaxf(oA.y, 0.f);
            oA.z = fmaxf(oA.z, 0.f); oA.w = fmaxf(oA.w, 0.f);
            oB.x = fmaxf(oB.x, 0.f); oB.y = fmaxf(oB.y, 0.f);
            oB.z = fmaxf(oB.z, 0.f); oB.w = fmaxf(oB.w, 0.f);
        }
        reinterpret_cast<float4*>(dst)[node * 4 + p * 2]     = oA;
        reinterpret_cast<float4*>(dst)[node * 4 + p * 2 + 1] = oB;
    }
}

// K6: hs2 = fp16( (act @ W2) * dinv[node] ). act is fp32 in d_out;
// result overwrites g_buf (hs1 is dead).
__global__ void k_gemm2(const float* __restrict__ act, const float* __restrict__ W2) {
    __shared__ float hs[16][HID];
    __shared__ float ws[HID][HID];
    const int t = threadIdx.x;
    const int r = t >> 4, c = t & 15;
    ws[r][c] = W2[t];
    const int node = blockIdx.x * 16 + r;
    hs[r][c] = act[node * HID + c];
    __syncthreads();
    float s = 0.0f;
    #pragma unroll
    for (int k = 0; k < HID; k++)
        s = fmaf(hs[r][k], ws[k][c], s);
    g_buf[node * HID + c] = __float2half(s * dinv_of(node));
}

extern "C" void kernel_launch(void* const* d_in, const int* in_sizes, int n_in,
                              void* d_out, int out_size) {
    const float* x   = (const float*)d_in[0];
    const void*  ei  = d_in[1];                 // [2,E] int64 OR int32 (detected)
    const float* W1  = (const float*)d_in[2];
    const float* b1  = (const float*)d_in[3];
    const float* W2  = (const float*)d_in[4];
    const float* b2  = (const float*)d_in[5];
    float*       out = (float*)d_out;

    const int nodeBlocks = (N_NODES + 255) / 256;          // 391
    const int edgeBlocks = (N_EDGES + 255) / 256;          // 12500
    const int rowBlocks  = N_NODES / 16;                   // 6250
    const int aggBlocks  = (N_NODES * 32 + 255) / 256;     // 12500

    k_zero   <<<nodeBlocks, 256>>>((const unsigned int*)ei);
    k_hist   <<<edgeBlocks, 256>>>(ei);

    // Fork: gemm1 (needs only g_cnt) overlaps scan+permute on side stream.
    cudaEventRecord(g_evFork, 0);
    cudaStreamWaitEvent(g_s2, g_evFork, 0);
    k_gemm1  <<<rowBlocks, 256, 0, g_s2>>>(x, W1);
    cudaEventRecord(g_evJoin, g_s2);

    k_scan1  <<<SCAN_BLOCKS, SB1>>>();
    k_scan2  <<<1, 256>>>();
    k_scan3  <<<nodeBlocks, 256>>>();
    k_permute<<<edgeBlocks, 256>>>(ei);

    // Join: agg1 needs both permute (main stream) and gemm1 (side stream).
    cudaStreamWaitEvent(0, g_evJoin, 0);

    k_agg    <<<aggBlocks, 256>>>(b1, out, 1);   // act -> d_out (scratch)
    k_gemm2  <<<rowBlocks, 256>>>(out, W2);      // hs2 -> g_buf (fp16)
    k_agg    <<<aggBlocks, 256>>>(b2, out, 0);   // final -> d_out
}

// round 16
// speedup vs baseline: 1.0645x; 1.0645x over previous
#include <cuda_runtime.h>

#define N_NODES 100000
#define N_EDGES 3200000
#define IN_DIM  128
#define HID     16
#define SB1     512
#define SCAN_BLOCKS ((N_NODES + SB1 - 1) / SB1)   // 196

// Scratch (device globals, ~20 MB). CRITICAL RULE (root cause of rounds 6-9
// failures): NEVER pass a __device__ symbol as a kernel argument from host
// code — the host-side shadow address gets passed, the kernel derefs a host
// VA, and HMM backs it with a 128 MiB device arena, tripping the harness
// mem-guard. All globals are referenced directly in device code.
__device__ __align__(16) float g_buf[N_NODES * HID];   // hs1, then hs2 (6.4 MB)
__device__ int g_srcs  [N_EDGES];                      // dst-sorted src ids (12.8 MB)
__device__ int g_cnt   [N_NODES];                      // in-degree
__device__ int g_cursor[N_NODES];                      // excl scan -> incl prefix
__device__ int g_bsum [SCAN_BLOCKS];
__device__ int g_bbase[256];
__device__ int g_is64;

// Fork-join stream/events, created at program load — BEFORE the harness's
// memory checkpoint and BEFORE graph capture starts. No device-memory APIs.
static cudaStream_t g_s2;
static cudaEvent_t  g_evFork, g_evJoin;
static struct _StreamInit {
    _StreamInit() {
        cudaStreamCreateWithFlags(&g_s2, cudaStreamNonBlocking);
        cudaEventCreateWithFlags(&g_evFork, cudaEventDisableTiming);
        cudaEventCreateWithFlags(&g_evJoin, cudaEventDisableTiming);
    }
} g_streamInit;

// ---------------------------------------------------------------------------
// K0: zero degree counts; thread 0 also detects edge_index dtype
// (int64 ids < 2^31 -> all odd 32-bit words zero).
__global__ void k_zero(const unsigned int* __restrict__ ei32) {
    int i = blockIdx.x * blockDim.x + threadIdx.x;
    if (i < N_NODES) g_cnt[i] = 0;
    if (i == 0) {
        int is64 = 1;
        #pragma unroll
        for (int k = 0; k < 64; k++)
            if (ei32[2 * k + 1] != 0u) { is64 = 0; break; }
        g_is64 = is64;
    }
}

// K1: in-degree histogram, 4 edges/thread (vector index loads, 4 independent
// atomic chains in flight — k_permute/k_hist were latency-bound at MLP=1:
// occ 82%, issue 6.2%).
__global__ void k_hist(const void* __restrict__ ei) {
    const int e4 = (blockIdx.x * blockDim.x + threadIdx.x) * 4;
    if (e4 >= N_EDGES) return;
    int d0, d1, d2, d3;
    if (g_is64) {
        const longlong4* p = reinterpret_cast<const longlong4*>(
            (const long long*)ei + N_EDGES);
        longlong4 d = p[e4 >> 2];
        d0 = (int)d.x; d1 = (int)d.y; d2 = (int)d.z; d3 = (int)d.w;
    } else {
        const int4* p = reinterpret_cast<const int4*>((const int*)ei + N_EDGES);
        int4 d = p[e4 >> 2];
        d0 = d.x; d1 = d.y; d2 = d.z; d3 = d.w;
    }
    atomicAdd(&g_cnt[d0], 1);
    atomicAdd(&g_cnt[d1], 1);
    atomicAdd(&g_cnt[d2], 1);
    atomicAdd(&g_cnt[d3], 1);
}

// dinv = rsqrt(deg+1), straight from g_cnt (+1 = self loop)
__device__ __forceinline__ float dinv_of(int i) {
    return rsqrtf((float)g_cnt[i] + 1.0f);
}

// K2a: per-block exclusive scan: read g_cnt, write g_cursor; sums -> g_bsum
__global__ void k_scan1() {
    __shared__ int sh[SB1];
    const int t = threadIdx.x;
    const int i = blockIdx.x * SB1 + t;
    int v = (i < N_NODES) ? g_cnt[i] : 0;
    sh[t] = v;
    __syncthreads();
    #pragma unroll
    for (int o = 1; o < SB1; o <<= 1) {
        int a = (t >= o) ? sh[t - o] : 0;
        __syncthreads();
        sh[t] += a;
        __syncthreads();
    }
    if (i < N_NODES) g_cursor[i] = sh[t] - v;            // local exclusive
    if (t == SB1 - 1) g_bsum[blockIdx.x] = sh[SB1 - 1];  // block total
}

// K2b: scan the block sums (single block, 256 >= 196)
__global__ void k_scan2() {
    __shared__ int sh[256];
    const int t = threadIdx.x;
    int v = (t < SCAN_BLOCKS) ? g_bsum[t] : 0;
    sh[t] = v;
    __syncthreads();
    #pragma unroll
    for (int o = 1; o < 256; o <<= 1) {
        int a = (t >= o) ? sh[t - o] : 0;
        __syncthreads();
        sh[t] += a;
        __syncthreads();
    }
    g_bbase[t] = sh[t] - v;
}

// K2c: add block bases -> global exclusive prefix (= segment starts)
__global__ void k_scan3() {
    int i = blockIdx.x * blockDim.x + threadIdx.x;
    if (i < N_NODES) g_cursor[i] += g_bbase[i / SB1];
}

// K3: permute src ids into dst-sorted order, 4 edges/thread (vector loads,
// 4 independent atomic+store chains). Cursors advance excl -> incl prefix.
__global__ void k_permute(const void* __restrict__ ei) {
    const int e4 = (blockIdx.x * blockDim.x + threadIdx.x) * 4;
    if (e4 >= N_EDGES) return;
    int s0, s1, s2, s3, d0, d1, d2, d3;
    if (g_is64) {
        const longlong4* ps = reinterpret_cast<const longlong4*>((const long long*)ei);
        const longlong4* pd = reinterpret_cast<const longlong4*>(
            (const long long*)ei + N_EDGES);
        longlong4 s = ps[e4 >> 2];
        longlong4 d = pd[e4 >> 2];
        s0 = (int)s.x; s1 = (int)s.y; s2 = (int)s.z; s3 = (int)s.w;
        d0 = (int)d.x; d1 = (int)d.y; d2 = (int)d.z; d3 = (int)d.w;
    } else {
        const int4* ps = reinterpret_cast<const int4*>((const int*)ei);
        const int4* pd = reinterpret_cast<const int4*>((const int*)ei + N_EDGES);
        int4 s = ps[e4 >> 2];
        int4 d = pd[e4 >> 2];
        s0 = s.x; s1 = s.y; s2 = s.z; s3 = s.w;
        d0 = d.x; d1 = d.y; d2 = d.z; d3 = d.w;
    }
    int p0 = atomicAdd(&g_cursor[d0], 1);
    int p1 = atomicAdd(&g_cursor[d1], 1);
    int p2 = atomicAdd(&g_cursor[d2], 1);
    int p3 = atomicAdd(&g_cursor[d3], 1);
    g_srcs[p0] = s0;
    g_srcs[p1] = s1;
    g_srcs[p2] = s2;
    g_srcs[p3] = s3;
}

// K4: hs1 = (x @ W1) * dinv[node] -> g_buf. 16 rows/block, 256 threads.
// Runs on the side stream, overlapped with scan+permute (needs only g_cnt).
__global__ void k_gemm1(const float* __restrict__ x, const float* __restrict__ W1) {
    __shared__ float xs[16][IN_DIM];
    __shared__ float ws[IN_DIM][HID];
    const int t = threadIdx.x;
    const int row0 = blockIdx.x * 16;

    #pragma unroll
    for (int i = t; i < IN_DIM * HID; i += 256)
        ws[i >> 4][i & 15] = W1[i];
    #pragma unroll
    for (int i = t; i < 16 * IN_DIM; i += 256)
        xs[i >> 7][i & 127] = x[row0 * IN_DIM + i];
    __syncthreads();

    const int r = t >> 4, c = t & 15;
    float s = 0.0f;
    #pragma unroll
    for (int k = 0; k < IN_DIM; k++)
        s = fmaf(xs[r][k], ws[k][c], s);

    const int node = row0 + r;
    g_buf[node * HID + c] = s * dinv_of(node);
}

// ---------------------------------------------------------------------------
// Shared gather+reduce core (fp32 — the fp16 variant regressed in R15):
// warp per node, no atomics, no per-edge norms.
__device__ __forceinline__ float4 warp_gather(const float* __restrict__ h,
                                              int start, int cnt, int lane, int q) {
    float4 acc = make_float4(0.f, 0.f, 0.f, 0.f);
    for (int base = 0; base < cnt; base += 32) {
        const int m = cnt - base;             // valid edges in this chunk
        int src_l = 0;                        // inert fill: weight 0
        float w_l = 0.0f;
        if (lane < m) { src_l = g_srcs[start + base + lane]; w_l = 1.0f; }
        #pragma unroll
        for (int r = 0; r < 4; r++) {
            if (8 * r >= m) break;            // uniform per warp
            const int j = (lane >> 2) + 8 * r;
            const int   src = __shfl_sync(0xffffffffu, src_l, j);
            const float w   = __shfl_sync(0xffffffffu, w_l,   j);
            float4 v = reinterpret_cast<const float4*>(h)[src * 4 + q];
            acc.x = fmaf(v.x, w, acc.x);
            acc.y = fmaf(v.y, w, acc.y);
            acc.z = fmaf(v.z, w, acc.z);
            acc.w = fmaf(v.w, w, acc.w);
        }
    }
    #pragma unroll
    for (int ofs = 4; ofs < 32; ofs <<= 1) {
        acc.x += __shfl_xor_sync(0xffffffffu, acc.x, ofs);
        acc.y += __shfl_xor_sync(0xffffffffu, acc.y, ofs);
        acc.z += __shfl_xor_sync(0xffffffffu, acc.z, ofs);
        acc.w += __shfl_xor_sync(0xffffffffu, acc.w, ofs);
    }
    return acc;
}

// K5: aggregation. dst[node] = (relu?)( bias + dinv*( hs[node] + sum hs[src] ) )
__global__ void k_agg(const float* __restrict__ bias,
                      float* __restrict__ dst,
                      int relu) {
    const int warp = (blockIdx.x * blockDim.x + threadIdx.x) >> 5;
    if (warp >= N_NODES) return;
    const float* __restrict__ h = g_buf;    // device symbol, device-side only
    const int lane = threadIdx.x & 31;
    const int node = warp;
    const int cnt   = g_cnt[node];
    const int start = g_cursor[node] - cnt; // cursor is inclusive after permute
    const int q     = lane & 3;
    const float dnode = rsqrtf((float)cnt + 1.0f);

    float4 acc = warp_gather(h, start, cnt, lane, q);

    if (lane < 4) {
        float4 self = reinterpret_cast<const float4*>(h)[node * 4 + q];
        float4 bv   = reinterpret_cast<const float4*>(bias)[q];
        float4 o;
        o.x = fmaf(acc.x + self.x, dnode, bv.x);
        o.y = fmaf(acc.y + self.y, dnode, bv.y);
        o.z = fmaf(acc.z + self.z, dnode, bv.z);
        o.w = fmaf(acc.w + self.w, dnode, bv.w);
        if (relu) {
            o.x = fmaxf(o.x, 0.f); o.y = fmaxf(o.y, 0.f);
            o.z = fmaxf(o.z, 0.f); o.w = fmaxf(o.w, 0.f);
        }
        reinterpret_cast<float4*>(dst)[node * 4 + q] = o;
    }
}

// K6: hs2 = (act @ W2) * dinv[node]. act lives in d_out (harness pointer);
// result overwrites g_buf (hs1 is dead).
__global__ void k_gemm2(const float* __restrict__ act, const float* __restrict__ W2) {
    __shared__ float hs[16][HID];
    __shared__ float ws[HID][HID];
    const int t = threadIdx.x;
    const int r = t >> 4, c = t & 15;
    ws[r][c] = W2[t];
    const int node = blockIdx.x * 16 + r;
    hs[r][c] = act[node * HID + c];
    __syncthreads();
    float s = 0.0f;
    #pragma unroll
    for (int k = 0; k < HID; k++)
        s = fmaf(hs[r][k], ws[k][c], s);
    g_buf[node * HID + c] = s * dinv_of(node);
}

extern "C" void kernel_launch(void* const* d_in, const int* in_sizes, int n_in,
                              void* d_out, int out_size) {
    const float* x   = (const float*)d_in[0];
    const void*  ei  = d_in[1];                 // [2,E] int64 OR int32 (detected)
    const float* W1  = (const float*)d_in[2];
    const float* b1  = (const float*)d_in[3];
    const float* W2  = (const float*)d_in[4];
    const float* b2  = (const float*)d_in[5];
    float*       out = (float*)d_out;

    const int nodeBlocks  = (N_NODES + 255) / 256;          // 391
    const int edge4Blocks = (N_EDGES / 4 + 255) / 256;      // 3125
    const int rowBlocks   = N_NODES / 16;                   // 6250
    const int aggBlocks   = (N_NODES * 32 + 255) / 256;     // 12500

    k_zero   <<<nodeBlocks, 256>>>((const unsigned int*)ei);
    k_hist   <<<edge4Blocks, 256>>>(ei);

    // Fork: gemm1 (needs only g_cnt) overlaps scan+permute on side stream.
    cudaEventRecord(g_evFork, 0);
    cudaStreamWaitEvent(g_s2, g_evFork, 0);
    k_gemm1  <<<rowBlocks, 256, 0, g_s2>>>(x, W1);
    cudaEventRecord(g_evJoin, g_s2);

    k_scan1  <<<SCAN_BLOCKS, SB1>>>();
    k_scan2  <<<1, 256>>>();
    k_scan3  <<<nodeBlocks, 256>>>();
    k_permute<<<edge4Blocks, 256>>>(ei);

    // Join: agg1 needs both permute (main stream) and gemm1 (side stream).
    cudaStreamWaitEvent(0, g_evJoin, 0);

    k_agg    <<<aggBlocks, 256>>>(b1, out, 1);   // act -> d_out (scratch)
    k_gemm2  <<<rowBlocks, 256>>>(out, W2);      // hs2 -> g_buf
    k_agg    <<<aggBlocks, 256>>>(b2, out, 0);   // final -> d_out
}